// round 12
// baseline (speedup 1.0000x reference)
#include <cuda_runtime.h>

// ---------------------------------------------------------------------------
// SSIM (5x5 Gaussian, sigma=1.5, SAME zero padding), fused single kernel.
// R12 = R11 + block-level double-buffered row staging:
//   - halo dedup: each thread loads only its own column (6 LDG, no clamp);
//     12 threads load the 4 halo cols x 3 channels. LDG issue 12 -> 8/step,
//     per-SM L1tex queue depth roughly halved.
//   - double buffer (parity s&1): ONE __syncthreads per step (WAR on a
//     buffer is guarded by the intervening step's barrier).
//   - keeps: (s,d) transform, masked horizontal weights, row peeling,
//     register ring, 1-row software prefetch.
// ---------------------------------------------------------------------------

constexpr int W    = 512;
constexpr int H    = 512;
constexpr int C    = 3;
constexpr int NB   = 16;
constexpr int BX   = 128;   // output columns per block (4 warps x 32)
constexpr int ROWS = 32;    // output rows per block

typedef unsigned long long u64;

__device__ __forceinline__ u64 pk2(float lo, float hi) {
    u64 r;
    asm("mov.b64 %0, {%1, %2};" : "=l"(r) : "f"(lo), "f"(hi));
    return r;
}
__device__ __forceinline__ void up2(u64 v, float& lo, float& hi) {
    asm("mov.b64 {%0, %1}, %2;" : "=f"(lo), "=f"(hi) : "l"(v));
}
__device__ __forceinline__ u64 fma2_(u64 a, u64 b, u64 c) {
    u64 d;
    asm("fma.rn.f32x2 %0, %1, %2, %3;" : "=l"(d) : "l"(a), "l"(b), "l"(c));
    return d;
}
__device__ __forceinline__ u64 mul2_(u64 a, u64 b) {
    u64 d;
    asm("mul.rn.f32x2 %0, %1, %2;" : "=l"(d) : "l"(a), "l"(b));
    return d;
}

__global__ __launch_bounds__(128, 4)
void ssim_kernel(const float* __restrict__ img1,
                 const float* __restrict__ img2,
                 const float* __restrict__ win,
                 float* __restrict__ out)
{
    // Block-wide double row buffer. Entry e holds col x0b + e - 2:
    // e=0,1 left halo, e=2..129 main (thread t -> e=2+t), e=130,131 right halo.
    __shared__ float2 buf[2][C][132];

    const int t    = threadIdx.x;          // 0..127
    const int b    = blockIdx.z;
    const int y0   = blockIdx.y * ROWS;
    const int x0b  = blockIdx.x * BX;
    const int xo   = x0b + t;              // own column (always in [0,W))

    // Halo duty: threads 0..11, one (channel, halo-col) each, both images.
    const bool duty   = (t < 12);
    const int  hc     = t >> 2;            // channel 0..2
    const int  hi     = t & 3;             // halo index 0..3
    const int  hcol   = (hi < 2) ? (x0b - 2 + hi) : (x0b + 126 + hi);
    const int  hentry = (hi < 2) ? hi : (128 + hi);
    const int  hcolc  = hcol < 0 ? 0 : (hcol > W - 1 ? W - 1 : hcol);

    // Separable 1D Gaussian: g[j] = w2d[2][j] / sqrt(w2d[2][2]).
    const float gc = sqrtf(win[12]);
    u64 wg[5];    // vertical weights (unmasked)
    u64 wgm[5];   // horizontal weights, masked by this lane's tap validity
#pragma unroll
    for (int j = 0; j < 5; ++j) {
        const float gj = __fdividef(win[10 + j], gc);
        wg[j] = pk2(gj, gj);
        const int tapcol = xo - 2 + j;
        const float mj = (tapcol >= 0 && tapcol < W) ? gj : 0.0f;
        wgm[j] = pk2(mj, mj);
    }

    int cb[C];
#pragma unroll
    for (int c = 0; c < C; ++c) cb[c] = ((b * C + c) * H) * W;

    // Rolling horizontal-filtered state: 5 row slots per channel (packed).
    u64 hSD[C][5], hSQ[C][5];

    // One-row-ahead prefetch registers.
    float pa[C], pb[C];    // own column, both images
    float h1, h2;          // halo value (duty threads only), both images

    auto loadrow_u = [&](int r) {       // interior rows: no checks at all
        const int rr = r * W;
#pragma unroll
        for (int c = 0; c < C; ++c) {
            const int o = cb[c] + rr + xo;
            pa[c] = img1[o];
            pb[c] = img2[o];
        }
        if (duty) {
            const int o = cb[hc] + rr + hcolc;
            h1 = img1[o];
            h2 = img2[o];
        }
    };
    auto loadrow_c = [&](int r) {       // top/bottom rows: zero if OOB
        const bool rok = (r >= 0) && (r < H);
        const int rr = (rok ? r : 0) * W;
        float ta[C], tb[C];
#pragma unroll
        for (int c = 0; c < C; ++c) {
            const int o = cb[c] + rr + xo;
            ta[c] = img1[o];
            tb[c] = img2[o];
        }
        float u1 = 0.0f, u2 = 0.0f;
        if (duty) {
            const int o = cb[hc] + rr + hcolc;
            u1 = img1[o];
            u2 = img2[o];
        }
#pragma unroll
        for (int c = 0; c < C; ++c) {
            pa[c] = rok ? ta[c] : 0.0f;
            pb[c] = rok ? tb[c] : 0.0f;
        }
        h1 = rok ? u1 : 0.0f;
        h2 = rok ? u2 : 0.0f;
    };

    const float C1 = 0.0001f;  // (0.01)^2
    const float C2 = 0.0009f;  // (0.03)^2

    // One pipeline step. s: runtime step id. S5 = s % 5 and P = s & 1 are
    // compile-time so the ring stays in registers and the buffer parity is
    // static. prefetch loads the row for step s+1.
    auto step = [&](int s, int S5, int P, auto&& prefetch) {
        // ---- store prefetched row s into buf[P] as (s,d) ----
#pragma unroll
        for (int c = 0; c < C; ++c)
            buf[P][c][2 + t] = make_float2(pa[c] + pb[c], pa[c] - pb[c]);
        if (duty)
            buf[P][hc][hentry] = make_float2(h1 + h2, h1 - h2);
        __syncthreads();

        // ---- prefetch next row (hidden behind compute below) ----
        prefetch();

        // ---- horizontal 5-tap pass into slot S5 (masked weights).
        //      Entry for tap j of column xo is t + j (unit stride). ----
#pragma unroll
        for (int c = 0; c < C; ++c) {
            const u64* p = (const u64*)&buf[P][c][0];
            u64 ssd = 0ull, ssq = 0ull;
#pragma unroll
            for (int j = 0; j < 5; ++j) {
                const u64 pp = p[t + j];
                ssd = fma2_(pp, wgm[j], ssd);
                ssq = fma2_(mul2_(pp, pp), wgm[j], ssq);
            }
            hSD[c][S5] = ssd;
            hSQ[c][S5] = ssq;
        }

        // ---- vertical 5-tap + epilogue for output row y0+s-4 ----
        if (s >= 4) {
            float num[C], den[C];
#pragma unroll
            for (int c = 0; c < C; ++c) {
                u64 vsd = 0ull, vsq = 0ull;
#pragma unroll
                for (int j = 0; j < 5; ++j) {
                    const int slot = (S5 + 1 + j) % 5;  // row s-4+j
                    vsd = fma2_(hSD[c][slot], wg[j], vsd);
                    vsq = fma2_(hSQ[c][slot], wg[j], vsq);
                }
                float cs, cd, css, csd;
                up2(vsd, cs, cd);     // conv(s), conv(d)
                up2(vsq, css, csd);   // conv(s^2), conv(d^2)
                const float cs2 = cs * cs, cd2 = cd * cd;
                const float m12 = (cs2 - cd2) * 0.25f;   // mu1*mu2
                const float msq = (cs2 + cd2) * 0.5f;    // mu1^2+mu2^2
                const float cab = (css - csd) * 0.25f;   // conv(ab)
                const float csum = (css + csd) * 0.5f;   // conv(a2)+conv(b2)
                const float s12  = cab - m12;            // sigma12
                const float svar = csum - msq;           // var1+var2
                num[c] = (2.0f * m12 + C1) * (2.0f * s12 + C2);
                den[c] = (msq + C1) * (svar + C2);
            }
            const float d01   = den[0] * den[1];
            const float denom = d01 * den[2];
            float numer = num[2] * d01;
            numer = fmaf(num[0], den[1] * den[2], numer);
            numer = fmaf(num[1], den[0] * den[2], numer);
            const int y = y0 + s - 4;
            out[(b * H + y) * W + xo] =
                __fdividef(numer, denom) * (1.0f / 3.0f);
        }
    };

    // ---- pipeline (S5 = s%5, P = s&1, all compile-time) ----
    loadrow_c(y0 - 2);                                // row for step 0
    step(0, 0, 0, [&] { loadrow_c(y0 - 1); });        // top, may be OOB
    step(1, 1, 1, [&] { loadrow_u(y0); });            // row y0 valid

    // Steady state: s = 2..31, rows y0+1..y0+30 always valid.
    // Unroll 10 so both s%5 and s&1 are static (base = 2,12,22: base%10==2).
    for (int base = 2; base < 32; base += 10) {
#pragma unroll
        for (int k = 0; k < 10; ++k) {
            step(base + k, (k + 2) % 5, k & 1,
                 [&] { loadrow_u(y0 - 1 + base + k); });
        }
    }

    step(32, 2, 0, [&] { loadrow_u(y0 + 31); });      // row y0+31 valid
    step(33, 3, 1, [&] { loadrow_c(y0 + 32); });      // bottom, may be OOB
    step(34, 4, 0, [&] { loadrow_c(y0 + 33); });      // bottom, may be OOB
    step(35, 0, 1, [&] {});                           // last step
}

extern "C" void kernel_launch(void* const* d_in, const int* in_sizes, int n_in,
                              void* d_out, int out_size)
{
    const float* img1 = (const float*)d_in[0];
    const float* img2 = (const float*)d_in[1];
    const float* win  = (const float*)d_in[2];
    float* out = (float*)d_out;

    dim3 grid(W / BX, H / ROWS, NB);  // (4, 16, 16) = 1024 blocks
    ssim_kernel<<<grid, 128>>>(img1, img2, win, out);
}